// round 6
// baseline (speedup 1.0000x reference)
#include <cuda_runtime.h>
#include <math.h>

#define TS   64
#define BB   32
#define VV   32000
#define HH   1024
#define EMBD 512
#define HB   32768
#define NB   148

typedef unsigned long long ull;

// ---------------- device scratch ----------------
__device__ float d_emb[(size_t)TS * EMBD * BB];   // [t][k][b]
__device__ float d_comb[HB];
__device__ float d_h0buf[2 * HB];                 // ping-pong h layer0
__device__ float d_h1i[HB];
__device__ float d_c0p[HB], d_c1p[HB];
__device__ float d_hbuf[(size_t)TS * HB];
__device__ float d_keys[(size_t)TS * HB];
__device__ float d_sc[TS * BB], d_dist[TS * BB], d_scp[32 * BB];
__device__ float d_sumv[HB];
__device__ float d_logits[(size_t)VV * BB];
__device__ float d_red[NB * 64];
__device__ float d_pmax[BB], d_pinv[BB], d_cwv[BB];
__device__ int   d_arrive, d_gen;

__device__ __forceinline__ float sigm(float x) { return 1.f / (1.f + expf(-x)); }

__device__ __forceinline__ void ffma2(ull& d, ull a, ull x) {
    asm("fma.rn.f32x2 %0, %1, %2, %0;" : "+l"(d) : "l"(a), "l"(x));
}
__device__ __forceinline__ ull pack2(float x) {
    ull r; unsigned int xi = __float_as_uint(x);
    asm("mov.b64 %0, {%1, %1};" : "=l"(r) : "r"(xi));
    return r;
}
__device__ __forceinline__ void unpack2(ull v, float& lo, float& hi) {
    unsigned int a, b;
    asm("mov.b64 {%0, %1}, %2;" : "=r"(a), "=r"(b) : "l"(v));
    lo = __uint_as_float(a); hi = __uint_as_float(b);
}

// software grid barrier (cooperative-groups pattern)
__device__ __forceinline__ void gridbar() {
    __syncthreads();
    if (threadIdx.x == 0) {
        int gen = *(volatile int*)&d_gen;
        __threadfence();
        if (atomicAdd(&d_arrive, 1) == NB - 1) {
            d_arrive = 0;
            __threadfence();
            *(volatile int*)&d_gen = gen + 1;
        } else {
            while (*(volatile int*)&d_gen == gen) __nanosleep(64);
            __threadfence();
        }
    }
    __syncthreads();
}

struct Seg { const float* A; const float* X; int lda; int nt; };

// 32-row GEMM accumulate into acc[2] (FFMA2 pairs). gatemap: local row r ->
// global row (r>>3)*1024 + base + (r&7); else base + r.
__device__ __forceinline__ void gemm32(const Seg* segs, int nseg, int gatemap,
                                       int base, float* s_as, ull* s_xs, ull* acc)
{
    const int tid  = threadIdx.x;
    const int b    = tid & 31, rg = tid >> 5;
    const int arow = tid >> 3, aq = (tid & 7) << 2, xk = tid >> 5;
    const int grow = gatemap ? ((arow >> 3) << 10) + base + (arow & 7) : base + arow;
    acc[0] = acc[1] = 0ull;
    int total = 0;
    for (int s = 0; s < nseg; s++) total += segs[s].nt;

    float4 av; float xv[4];
    auto fetch = [&](int g) {
        int s = 0;
        while (g >= segs[s].nt) { g -= segs[s].nt; s++; }
        const int k0 = g << 5;
        av = *(const float4*)(segs[s].A + (size_t)grow * segs[s].lda + k0 + aq);
#pragma unroll
        for (int i = 0; i < 4; i++)
            xv[i] = segs[s].X[(size_t)(k0 + xk + 8 * i) * BB + b];
    };

    int buf = 0;
    fetch(0);
    for (int g = 0; g < total; g++) {
        float* A_ = s_as + buf * (32 * 36);
        ull*   X_ = s_xs + buf * (32 * 33);
        A_[(aq + 0) * 36 + arow] = av.x;
        A_[(aq + 1) * 36 + arow] = av.y;
        A_[(aq + 2) * 36 + arow] = av.z;
        A_[(aq + 3) * 36 + arow] = av.w;
#pragma unroll
        for (int i = 0; i < 4; i++)
            X_[(xk + 8 * i) * 33 + b] = pack2(xv[i]);
        __syncthreads();
        if (g + 1 < total) fetch(g + 1);
#pragma unroll
        for (int kk = 0; kk < 32; kk++) {
            ull xp = X_[kk * 33 + b];
            ulonglong2 u = *(const ulonglong2*)(A_ + kk * 36 + rg * 4);
            ffma2(acc[0], u.x, xp);
            ffma2(acc[1], u.y, xp);
        }
        buf ^= 1;
        __syncthreads();
    }
}

__global__ void __launch_bounds__(256) mega(
    const int* __restrict__ toks, const float* __restrict__ h0,
    const float* __restrict__ c0, const float* __restrict__ E,
    const float* __restrict__ Wih0, const float* __restrict__ Whh0,
    const float* __restrict__ bih0, const float* __restrict__ bhh0,
    const float* __restrict__ Wih1, const float* __restrict__ Whh1,
    const float* __restrict__ bih1, const float* __restrict__ bhh1,
    const float* __restrict__ Wk, const float* __restrict__ bk,
    const float* __restrict__ Wc, const float* __restrict__ bc,
    const float* __restrict__ Wp, const float* __restrict__ bp,
    float* __restrict__ out)
{
    __shared__ __align__(16) float s_as[2 * 32 * 68];
    __shared__ ull   s_xs[2 * 32 * 33];
    __shared__ float s_g[32 * 33];
    __shared__ float s_r1[8 * 33];
    __shared__ float s_r2[8 * 33];

    const int bi  = blockIdx.x;
    const int tid = threadIdx.x;
    const int b   = tid & 31, rg = tid >> 5;

    // ---- init: embeddings, state transpose ----
    for (int gi = bi * 256 + tid; gi < TS * EMBD * BB; gi += NB * 256) {
        int bb = gi & 31, k = (gi >> 5) & (EMBD - 1), t = gi >> 14;
        d_emb[gi] = E[(size_t)toks[t * BB + bb] * EMBD + k];
    }
    for (int gi = bi * 256 + tid; gi < HB; gi += NB * 256) {
        int h = gi >> 5, bb = gi & 31;
        d_h0buf[gi] = h0[(size_t)bb * HH + h];
        d_h1i[gi]   = h0[(size_t)(BB + bb) * HH + h];
        d_c0p[gi]   = c0[(size_t)bb * HH + h];
        d_c1p[gi]   = c0[(size_t)(BB + bb) * HH + h];
        d_comb[gi]  = 0.f;
    }
    gridbar();

    for (int t = 0; t < TS; t++) {
        const float* emb_t  = d_emb + (size_t)t * EMBD * BB;
        float*       htop   = d_hbuf + (size_t)t * HB;
        const float* h1prev = t ? d_hbuf + (size_t)(t - 1) * HB : d_h1i;
        float*       h0prev = d_h0buf + (t & 1) * HB;
        float*       h0new  = d_h0buf + ((t + 1) & 1) * HB;

        // ======== P1: LSTM0 (bi<128) + fixup(t-1) (bi>=128) ========
        if (bi < 128) {
            Seg segs[3] = { {Wih0, emb_t, 1536, 16}, {Wih0 + 512, d_comb, 1536, 32},
                            {Whh0, h0prev, 1024, 32} };
            ull acc[2];
            gemm32(segs, 3, 1, bi * 8, s_as, s_xs, acc);
#pragma unroll
            for (int p = 0; p < 2; p++) {
                float lo, hi; unpack2(acc[p], lo, hi);
                int r = rg * 4 + 2 * p;
                int grow = ((r >> 3) << 10) + bi * 8 + (r & 7);
                lo += bih0[grow] + bhh0[grow];
                hi += bih0[grow + 1] + bhh0[grow + 1];
                s_g[r * 33 + b] = lo;
                s_g[(r + 1) * 33 + b] = hi;
            }
            __syncthreads();
            {
                int hloc = tid >> 5, b2 = tid & 31;
                int i = (bi * 8 + hloc) * 32 + b2;
                float gi_ = s_g[hloc * 33 + b2];
                float gf  = s_g[(8 + hloc) * 33 + b2];
                float gg  = s_g[(16 + hloc) * 33 + b2];
                float go  = s_g[(24 + hloc) * 33 + b2];
                float c2 = sigm(gf) * d_c0p[i] + sigm(gi_) * tanhf(gg);
                d_c0p[i] = c2;
                h0new[i] = sigm(go) * tanhf(c2);
            }
        } else if (t > 0) {
            // fixup for step t-1 (blocks 128..147), dist/logits/pmax of t-1 still live
            int tp = t - 1;
            for (int s = bi - 128; s <= tp; s += 20) {
                if (tid < 32) {
                    int bb = tid;
                    int v = toks[s * BB + bb];
                    bool first = true;
                    for (int sp = 0; sp < s; sp++)
                        if (toks[sp * BB + bb] == v) { first = false; break; }
                    if (first) {
                        float S = 0.f;
                        for (int sp = s; sp <= tp; sp++)
                            if (toks[sp * BB + bb] == v) S += d_dist[sp * BB + bb];
                        float pv = expf(d_logits[(size_t)v * BB + bb] - d_pmax[bb]) * d_pinv[bb];
                        float c = d_cwv[bb];
                        out[(size_t)(tp * BB + bb) * VV + v] =
                            logf(c * (1e-7f + S) + (1.f - c) * pv);
                    }
                }
            }
        }
        gridbar();

        // ======== P2: LSTM1 (bi<128) ========
        if (bi < 128) {
            Seg segs[2] = { {Wih1, h0new, 1024, 32}, {Whh1, h1prev, 1024, 32} };
            ull acc[2];
            gemm32(segs, 2, 1, bi * 8, s_as, s_xs, acc);
#pragma unroll
            for (int p = 0; p < 2; p++) {
                float lo, hi; unpack2(acc[p], lo, hi);
                int r = rg * 4 + 2 * p;
                int grow = ((r >> 3) << 10) + bi * 8 + (r & 7);
                lo += bih1[grow] + bhh1[grow];
                hi += bih1[grow + 1] + bhh1[grow + 1];
                s_g[r * 33 + b] = lo;
                s_g[(r + 1) * 33 + b] = hi;
            }
            __syncthreads();
            {
                int hloc = tid >> 5, b2 = tid & 31;
                int i = (bi * 8 + hloc) * 32 + b2;
                float gi_ = s_g[hloc * 33 + b2];
                float gf  = s_g[(8 + hloc) * 33 + b2];
                float gg  = s_g[(16 + hloc) * 33 + b2];
                float go  = s_g[(24 + hloc) * 33 + b2];
                float c2 = sigm(gf) * d_c1p[i] + sigm(gi_) * tanhf(gg);
                d_c1p[i] = c2;
                htop[i] = sigm(go) * tanhf(c2);
            }
        }
        gridbar();

        // ======== P3: keys[t] (bi<32) + scores s<t (32<=bi<32+t) ========
        if (bi < 32) {
            Seg segs[1] = { {Wk, htop, 1024, 32} };
            ull acc[2];
            gemm32(segs, 1, 0, bi * 32, s_as, s_xs, acc);
            float psum = 0.f;
#pragma unroll
            for (int p = 0; p < 2; p++) {
                float lo, hi; unpack2(acc[p], lo, hi);
                int j = bi * 32 + rg * 4 + 2 * p;
                lo += bk[j]; hi += bk[j + 1];
                d_keys[(size_t)t * HB + j * 32 + b] = lo;
                d_keys[(size_t)t * HB + (j + 1) * 32 + b] = hi;
                psum = fmaf(lo, htop[j * 32 + b], psum);
                psum = fmaf(hi, htop[(j + 1) * 32 + b], psum);
            }
            s_r1[rg * 33 + b] = psum;
            __syncthreads();
            if (tid < 32) {
                float v = 0.f;
#pragma unroll
                for (int r = 0; r < 8; r++) v += s_r1[r * 33 + tid];
                d_scp[bi * 32 + tid] = v;
            }
        } else if (bi >= 32 && bi < 32 + t) {
            int s = bi - 32;
            const float* ks = d_keys + (size_t)s * HB;
            float acc = 0.f;
            for (int h = rg; h < HH; h += 8)
                acc = fmaf(ks[h * 32 + b], htop[h * 32 + b], acc);
            s_r1[rg * 33 + b] = acc;
            __syncthreads();
            if (tid < 32) {
                float v = 0.f;
#pragma unroll
                for (int r = 0; r < 8; r++) v += s_r1[r * 33 + tid];
                if (toks[s * BB + tid] == 0) v -= 99999.f;
                d_sc[s * BB + tid] = v;
            }
        }
        gridbar();

        // ======== P4: summary + softmax + dist ========
        {
            int gi = bi * 256 + tid;
            if (gi < HB) {
                int bb = gi & 31;
                float sct = 0.f;
#pragma unroll 8
                for (int p = 0; p < 32; p++) sct += d_scp[p * 32 + bb];
                if (toks[t * BB + bb] == 0) sct -= 99999.f;
                float m = sct;
                for (int s = 0; s < t; s++) m = fmaxf(m, d_sc[s * BB + bb]);
                float ssum = expf(sct - m);
                for (int s = 0; s < t; s++) ssum += expf(d_sc[s * BB + bb] - m);
                float inv = 1.f / ssum;
                float acc = 0.f;
                for (int s = 0; s < t; s++)
                    acc = fmaf(expf(d_sc[s * BB + bb] - m) * inv,
                               d_hbuf[(size_t)s * HB + gi], acc);
                acc = fmaf(expf(sct - m) * inv, htop[gi], acc);
                d_sumv[gi] = acc;
                if (gi < 32) {
                    for (int s = 0; s < t; s++)
                        d_dist[s * BB + gi] = expf(d_sc[s * BB + gi] - m) * inv;
                    d_dist[t * BB + gi] = expf(sct - m) * inv;
                }
            }
        }
        gridbar();

        // ======== P5: comb (bi<32) ========
        if (bi < 32) {
            Seg segs[2] = { {Wc, htop, 2048, 32}, {Wc + 1024, d_sumv, 2048, 32} };
            ull acc[2];
            gemm32(segs, 2, 0, bi * 32, s_as, s_xs, acc);
#pragma unroll
            for (int p = 0; p < 2; p++) {
                float lo, hi; unpack2(acc[p], lo, hi);
                int j = bi * 32 + rg * 4 + 2 * p;
                d_comb[j * 32 + b] = lo + bc[j];
                d_comb[(j + 1) * 32 + b] = hi + bc[j + 1];
            }
        }
        gridbar();

        // ======== P6: logits (all blocks, JT=64 tiles strided) + online (m,s) ====
        {
            const int arow = tid >> 3, aq = (tid & 7) << 2, xk = tid >> 5;
            float om = -1e30f, os = 0.f;
            for (int tile = bi; tile < VV / 64; tile += NB) {
                const int j0 = tile * 64;
                ull acc4[4] = {0ull, 0ull, 0ull, 0ull};
                float4 av0, av1; float xv[4];
                auto fetch = [&](int g) {
                    const int k0 = g << 5;
                    av0 = *(const float4*)(Wp + (size_t)(j0 + arow) * 1024 + k0 + aq);
                    av1 = *(const float4*)(Wp + (size_t)(j0 + arow + 32) * 1024 + k0 + aq);
#pragma unroll
                    for (int i = 0; i < 4; i++)
                        xv[i] = d_comb[(size_t)(k0 + xk + 8 * i) * BB + b];
                };
                int buf = 0;
                fetch(0);
                for (int g = 0; g < 32; g++) {
                    float* A_ = s_as + buf * (32 * 68);
                    ull*   X_ = s_xs + buf * (32 * 33);
                    A_[(aq + 0) * 68 + arow] = av0.x;
                    A_[(aq + 1) * 68 + arow] = av0.y;
                    A_[(aq + 2) * 68 + arow] = av0.z;
                    A_[(aq + 3) * 68 + arow] = av0.w;
                    A_[(aq + 0) * 68 + arow + 32] = av1.x;
                    A_[(aq + 1) * 68 + arow + 32] = av1.y;
                    A_[(aq + 2) * 68 + arow + 32] = av1.z;
                    A_[(aq + 3) * 68 + arow + 32] = av1.w;
#pragma unroll
                    for (int i = 0; i < 4; i++)
                        X_[(xk + 8 * i) * 33 + b] = pack2(xv[i]);
                    __syncthreads();
                    if (g + 1 < 32) fetch(g + 1);
#pragma unroll
                    for (int kk = 0; kk < 32; kk++) {
                        ull xp = X_[kk * 33 + b];
                        const float* ab = A_ + kk * 68 + rg * 8;
                        ulonglong2 u0 = *(const ulonglong2*)(ab);
                        ulonglong2 u1 = *(const ulonglong2*)(ab + 4);
                        ffma2(acc4[0], u0.x, xp);
                        ffma2(acc4[1], u0.y, xp);
                        ffma2(acc4[2], u1.x, xp);
                        ffma2(acc4[3], u1.y, xp);
                    }
                    buf ^= 1;
                    __syncthreads();
                }
#pragma unroll
                for (int p = 0; p < 4; p++) {
                    float lo, hi; unpack2(acc4[p], lo, hi);
                    int j = j0 + rg * 8 + 2 * p;
                    lo += bp[j]; hi += bp[j + 1];
                    d_logits[(size_t)j * BB + b] = lo;
                    d_logits[(size_t)(j + 1) * BB + b] = hi;
                    float m2 = fmaxf(om, lo);
                    os = os * expf(om - m2) + expf(lo - m2); om = m2;
                    m2 = fmaxf(om, hi);
                    os = os * expf(om - m2) + expf(hi - m2); om = m2;
                }
            }
            s_r1[rg * 33 + b] = om;
            s_r2[rg * 33 + b] = os;
            __syncthreads();
            if (tid < 32) {
                float m = -1e30f, s = 0.f;
#pragma unroll
                for (int r = 0; r < 8; r++) {
                    float pm = s_r1[r * 33 + tid], ps = s_r2[r * 33 + tid];
                    float m2 = fmaxf(m, pm);
                    s = s * expf(m - m2) + ps * expf(pm - m2);
                    m = m2;
                }
                d_red[bi * 64 + tid] = m;
                d_red[bi * 64 + 32 + tid] = s;
            }
            __syncthreads();
        }
        gridbar();

        // ======== P7: final softmax scalars + out ========
        {
            if (tid < 32) {
                float m = -1e30f, s = 0.f;
                for (int i = 0; i < NB; i++) {
                    float pm = d_red[i * 64 + tid], ps = d_red[i * 64 + 32 + tid];
                    float m2 = fmaxf(m, pm);
                    s = s * expf(m - m2) + ps * expf(pm - m2);
                    m = m2;
                }
                float inv = 1.f / s;
                float cwv = expf(d_logits[3 * BB + tid] - m) * inv;
                s_r1[tid] = m; s_r1[32 + tid] = inv; s_r1[64 + tid] = cwv;
                if (bi == 0) { d_pmax[tid] = m; d_pinv[tid] = inv; d_cwv[tid] = cwv; }
            }
            __syncthreads();
            float m   = s_r1[tid & 31];
            float inv = s_r1[32 + (tid & 31)];
            float c   = s_r1[64 + (tid & 31)];
            float ce = c * 1e-7f, l1c = 1.f - c;
            float* tile = s_as;   // reuse as [128][33]
            for (int chunk = bi; chunk < VV / 128; chunk += NB) {
                int v0 = chunk * 128;
                int lane = tid & 31, w = tid >> 5;
#pragma unroll
                for (int k = 0; k < 16; k++) {
                    int vr = (k << 3) + w;
                    float pv = expf(d_logits[(size_t)(v0 + vr) * BB + lane] - m) * inv;
                    tile[vr * 33 + lane] = logf(ce + l1c * pv);
                }
                __syncthreads();
                int bo = tid >> 3, q = tid & 7;
                float* op = out + (size_t)(t * BB + bo) * VV + v0;
#pragma unroll
                for (int i = 0; i < 4; i++) {
                    int vb = (q + (i << 3)) << 2;
                    *(float4*)(op + vb) = make_float4(tile[vb * 33 + bo],
                                                      tile[(vb + 1) * 33 + bo],
                                                      tile[(vb + 2) * 33 + bo],
                                                      tile[(vb + 3) * 33 + bo]);
                }
                __syncthreads();
            }
        }
        gridbar();
    }

    // final fixup for t = TS-1
    if (bi >= 128) {
        int tp = TS - 1;
        for (int s = bi - 128; s <= tp; s += 20) {
            if (tid < 32) {
                int bb = tid;
                int v = toks[s * BB + bb];
                bool first = true;
                for (int sp = 0; sp < s; sp++)
                    if (toks[sp * BB + bb] == v) { first = false; break; }
                if (first) {
                    float S = 0.f;
                    for (int sp = s; sp <= tp; sp++)
                        if (toks[sp * BB + bb] == v) S += d_dist[sp * BB + bb];
                    float pv = expf(d_logits[(size_t)v * BB + bb] - d_pmax[bb]) * d_pinv[bb];
                    float c = d_cwv[bb];
                    out[(size_t)(tp * BB + bb) * VV + v] =
                        logf(c * (1e-7f + S) + (1.f - c) * pv);
                }
            }
        }
    }
}

// ---------------- host ----------------
extern "C" void kernel_launch(void* const* d_in, const int* in_sizes, int n_in,
                              void* d_out, int out_size)
{
    mega<<<NB, 256>>>(
        (const int*)d_in[0], (const float*)d_in[1], (const float*)d_in[2],
        (const float*)d_in[3], (const float*)d_in[4], (const float*)d_in[5],
        (const float*)d_in[6], (const float*)d_in[7], (const float*)d_in[8],
        (const float*)d_in[9], (const float*)d_in[10], (const float*)d_in[11],
        (const float*)d_in[12], (const float*)d_in[13], (const float*)d_in[14],
        (const float*)d_in[15], (const float*)d_in[16], (const float*)d_in[17],
        (float*)d_out);
}

// round 7
// speedup vs baseline: 1.5288x; 1.5288x over previous
#include <cuda_runtime.h>
#include <math.h>

#define TS   64
#define BB   32
#define VV   32000
#define HH   1024
#define EMBD 512
#define G4   4096
#define HB   32768          // HH*BB

typedef unsigned long long ull;

// ---------------- device scratch ----------------
__device__ float d_emb[(size_t)TS * EMBD * BB];   // [t][k][b]
__device__ float d_comb[2 * HB];                  // ping-pong by t&1
__device__ float d_h0p[HB];
__device__ float d_h1i[HB];
__device__ float d_c0p[HB], d_c1p[HB];
__device__ float d_g[4 * (size_t)G4 * BB];        // 4 partial planes
__device__ float d_kp[4 * (size_t)HB];            // key partials
__device__ float d_cp[4 * (size_t)HB];            // comb partials
__device__ float d_hbuf[(size_t)TS * HB];
__device__ float d_keys[(size_t)TS * HB];
__device__ float d_sc[TS * BB];
__device__ float d_dist[2 * TS * BB];             // ping-pong by t&1
__device__ float d_sumv[HB];
__device__ float d_pexp[(size_t)VV * BB];         // exp(logit), [v][b]
__device__ float d_red[500 * BB];
__device__ float d_ce[BB], d_f[BB], d_cw[BB];

__device__ __forceinline__ float sigm(float x) { return 1.f / (1.f + expf(-x)); }

__device__ __forceinline__ void ffma2(ull& d, ull a, ull x) {
    asm("fma.rn.f32x2 %0, %1, %2, %0;" : "+l"(d) : "l"(a), "l"(x));
}
__device__ __forceinline__ ull pack2(float x) {
    ull r; unsigned int xi = __float_as_uint(x);
    asm("mov.b64 %0, {%1, %1};" : "=l"(r) : "r"(xi));
    return r;
}
__device__ __forceinline__ void unpack2(ull v, float& lo, float& hi) {
    unsigned int a, b;
    asm("mov.b64 {%0, %1}, %2;" : "=r"(a), "=r"(b) : "l"(v));
    lo = __uint_as_float(a); hi = __uint_as_float(b);
}

// ---------------- tiled GEMM with k-split over gridDim.y (R5, proven) -------
template<int JT>
__global__ void __launch_bounds__(256) k_gemm(
    const float* __restrict__ A0, const float* __restrict__ X0, int lda0, int t0,
    const float* __restrict__ A1, const float* __restrict__ X1, int lda1, int t1,
    const float* __restrict__ A2, const float* __restrict__ X2, int lda2, int t2,
    int tps, const float* __restrict__ bias1, const float* __restrict__ bias2,
    float* __restrict__ out, long long outPlane)
{
    constexpr int R   = JT / 8;
    constexpr int PR  = R / 2;
    constexpr int AST = JT + 4;
    constexpr int NCH = JT / 32;

    __shared__ __align__(16) float As[2][32 * AST];
    __shared__ float Xs[2][32 * 33];

    const int tid  = threadIdx.x;
    const int b    = tid & 31;
    const int rg   = tid >> 5;
    const int j0   = blockIdx.x * JT;
    const int arow = tid >> 3;
    const int aq   = (tid & 7) << 2;
    const int xk   = tid >> 5;

    const int total = t0 + t1 + t2;
    const int g0 = blockIdx.y * tps;
    const int g1 = min(total, g0 + tps);

    ull acc[PR];
#pragma unroll
    for (int p = 0; p < PR; p++) acc[p] = 0ull;

    float4 av[NCH];
    float  xv[4];

    auto fetch = [&](int g) {
        const float* A; const float* X; int lda, lk;
        if (g < t0)            { A = A0; X = X0; lda = lda0; lk = g; }
        else if (g < t0 + t1)  { A = A1; X = X1; lda = lda1; lk = g - t0; }
        else                   { A = A2; X = X2; lda = lda2; lk = g - t0 - t1; }
        const int k0 = lk << 5;
#pragma unroll
        for (int c = 0; c < NCH; c++)
            av[c] = *(const float4*)(A + (size_t)(j0 + arow + 32 * c) * lda + k0 + aq);
#pragma unroll
        for (int i = 0; i < 4; i++)
            xv[i] = X[(size_t)(k0 + xk + 8 * i) * BB + b];
    };

    int buf = 0;
    if (g0 < g1) fetch(g0);
    for (int g = g0; g < g1; g++) {
#pragma unroll
        for (int c = 0; c < NCH; c++) {
            const int r = arow + 32 * c;
            As[buf][(aq + 0) * AST + r] = av[c].x;
            As[buf][(aq + 1) * AST + r] = av[c].y;
            As[buf][(aq + 2) * AST + r] = av[c].z;
            As[buf][(aq + 3) * AST + r] = av[c].w;
        }
#pragma unroll
        for (int i = 0; i < 4; i++)
            Xs[buf][(xk + 8 * i) * 33 + b] = xv[i];
        __syncthreads();

        if (g + 1 < g1) fetch(g + 1);

#pragma unroll
        for (int kk = 0; kk < 32; kk++) {
            ull xp = pack2(Xs[buf][kk * 33 + b]);
            const float* ab = &As[buf][kk * AST + rg * R];
#pragma unroll
            for (int q = 0; q < PR / 2; q++) {
                ulonglong2 u = *(const ulonglong2*)(ab + (q << 2));
                ffma2(acc[2 * q],     u.x, xp);
                ffma2(acc[2 * q + 1], u.y, xp);
            }
        }
        buf ^= 1;
        __syncthreads();
    }

    float* outp = out + blockIdx.y * outPlane;
#pragma unroll
    for (int p = 0; p < PR; p++) {
        float lo, hi;
        unpack2(acc[p], lo, hi);
        const int j = j0 + rg * R + 2 * p;
        if (blockIdx.y == 0) {
            if (bias1) { lo += bias1[j]; hi += bias1[j + 1]; }
            if (bias2) { lo += bias2[j]; hi += bias2[j + 1]; }
        }
        outp[(size_t)j * BB + b]       = lo;
        outp[(size_t)(j + 1) * BB + b] = hi;
    }
}

// ---------------- logits GEMM + exp epilogue + per-block sum ----------------
__global__ void __launch_bounds__(256) k_logits(
    const float* __restrict__ Wp, const float* __restrict__ comb,
    const float* __restrict__ bp, float* __restrict__ pexp, float* __restrict__ red)
{
    __shared__ __align__(16) float As[2][32 * 68];
    __shared__ ull   Xs[2][32 * 33];
    __shared__ float sr[8][33];

    const int tid  = threadIdx.x;
    const int b    = tid & 31, rg = tid >> 5;
    const int j0   = blockIdx.x * 64;
    const int arow = tid >> 3, aq = (tid & 7) << 2, xk = tid >> 5;

    ull acc4[4] = {0ull, 0ull, 0ull, 0ull};
    float4 av0, av1; float xv[4];
    auto fetch = [&](int g) {
        const int k0 = g << 5;
        av0 = *(const float4*)(Wp + (size_t)(j0 + arow) * 1024 + k0 + aq);
        av1 = *(const float4*)(Wp + (size_t)(j0 + arow + 32) * 1024 + k0 + aq);
#pragma unroll
        for (int i = 0; i < 4; i++)
            xv[i] = comb[(size_t)(k0 + xk + 8 * i) * BB + b];
    };
    int buf = 0;
    fetch(0);
    for (int g = 0; g < 32; g++) {
        float* A_ = As[buf];
        ull*   X_ = Xs[buf];
        A_[(aq + 0) * 68 + arow] = av0.x;
        A_[(aq + 1) * 68 + arow] = av0.y;
        A_[(aq + 2) * 68 + arow] = av0.z;
        A_[(aq + 3) * 68 + arow] = av0.w;
        A_[(aq + 0) * 68 + arow + 32] = av1.x;
        A_[(aq + 1) * 68 + arow + 32] = av1.y;
        A_[(aq + 2) * 68 + arow + 32] = av1.z;
        A_[(aq + 3) * 68 + arow + 32] = av1.w;
#pragma unroll
        for (int i = 0; i < 4; i++)
            X_[(xk + 8 * i) * 33 + b] = pack2(xv[i]);
        __syncthreads();
        if (g + 1 < 32) fetch(g + 1);
#pragma unroll
        for (int kk = 0; kk < 32; kk++) {
            ull xp = X_[kk * 33 + b];
            const float* ab = A_ + kk * 68 + rg * 8;
            ulonglong2 u0 = *(const ulonglong2*)(ab);
            ulonglong2 u1 = *(const ulonglong2*)(ab + 4);
            ffma2(acc4[0], u0.x, xp);
            ffma2(acc4[1], u0.y, xp);
            ffma2(acc4[2], u1.x, xp);
            ffma2(acc4[3], u1.y, xp);
        }
        buf ^= 1;
        __syncthreads();
    }
    float psum = 0.f;
#pragma unroll
    for (int p = 0; p < 4; p++) {
        float lo, hi; unpack2(acc4[p], lo, hi);
        int j = j0 + rg * 8 + 2 * p;
        float e0 = expf(lo + bp[j]);
        float e1 = expf(hi + bp[j + 1]);
        pexp[(size_t)j * BB + b]       = e0;
        pexp[(size_t)(j + 1) * BB + b] = e1;
        psum += e0 + e1;
    }
    sr[rg][b] = psum;
    __syncthreads();
    if (tid < 32) {
        float v = 0.f;
#pragma unroll
        for (int r = 0; r < 8; r++) v += sr[r][tid];
        red[blockIdx.x * BB + tid] = v;
    }
}

// ---------------- embed all timesteps once ----------------
__global__ void k_embed_all(const float* __restrict__ E, const int* __restrict__ toks,
                            float* __restrict__ emb)
{
    int i = blockIdx.x * 256 + threadIdx.x;
    int b = i & 31, k = (i >> 5) & (EMBD - 1), t = i >> 14;
    emb[i] = E[(size_t)toks[t * BB + b] * EMBD + k];
}

// ---------------- init ----------------
__global__ void k_init(const float* __restrict__ h0, const float* __restrict__ c0,
                       float* h0p, float* h1i, float* c0p, float* c1p, float* comb)
{
    int i = blockIdx.x * 256 + threadIdx.x;
    int h = i >> 5, b = i & 31;
    h0p[i]  = h0[(size_t)b * HH + h];
    h1i[i]  = h0[(size_t)(BB + b) * HH + h];
    c0p[i]  = c0[(size_t)b * HH + h];
    c1p[i]  = c0[(size_t)(BB + b) * HH + h];
    comb[i] = 0.f;
    comb[HB + i] = 0.f;
}

// ---------------- LSTM gates: sum 4 partial planes + nonlinearity ----------------
__global__ void k_gates(const float* __restrict__ gp, float* __restrict__ c,
                        float* __restrict__ hout)
{
    int i = blockIdx.x * 256 + threadIdx.x;
    float g[4];
#pragma unroll
    for (int m = 0; m < 4; m++) {
        size_t o = (size_t)m * HB + i;
        g[m] = gp[o] + gp[(size_t)G4 * BB + o] + gp[2 * (size_t)G4 * BB + o]
             + gp[3 * (size_t)G4 * BB + o];
    }
    float c2 = sigm(g[1]) * c[i] + sigm(g[0]) * tanhf(g[2]);
    c[i] = c2;
    hout[i] = sigm(g[3]) * tanhf(c2);
}

// ---------------- scores (+ finalize keys[t] from partials at s==t) ----------------
__global__ void __launch_bounds__(256) k_scores(float* __restrict__ keys,
        const float* __restrict__ kp, const float* __restrict__ htop,
        const int* __restrict__ toks, float* __restrict__ sc, int t)
{
    int s = blockIdx.x;
    int lane = threadIdx.x & 31, w = threadIdx.x >> 5;
    float acc = 0.f;
    if (s == t) {
        float* kf = keys + (size_t)t * HB;
        for (int h = w; h < HH; h += 8) {
            int i = h * BB + lane;
            float v = kp[i] + kp[HB + i] + kp[2 * HB + i] + kp[3 * HB + i];
            kf[i] = v;
            acc = fmaf(v, htop[i], acc);
        }
    } else {
        const float* ks = keys + (size_t)s * HB;
        for (int h = w; h < HH; h += 8)
            acc = fmaf(ks[h * BB + lane], htop[h * BB + lane], acc);
    }
    __shared__ float red[8][BB];
    red[w][lane] = acc;
    __syncthreads();
    if (w == 0) {
        float v = acc;
#pragma unroll
        for (int r = 1; r < 8; r++) v += red[r][lane];
        if (toks[s * BB + lane] == 0) v -= 99999.f;
        sc[s * BB + lane] = v;
    }
}

// ---------------- summary: per-block softmax in smem (MUFU once), FMA loop ----
__global__ void k_summary(const float* __restrict__ sc, const float* __restrict__ hbuf,
                          int t, float* __restrict__ dist, float* __restrict__ sum)
{
    __shared__ float sd[TS * BB];
    int tid = threadIdx.x;
    if (tid < 32) {
        int b = tid;
        float m = -1e30f;
        for (int s = 0; s <= t; s++) m = fmaxf(m, sc[s * BB + b]);
        float ss = 0.f;
        for (int s = 0; s <= t; s++) {
            float e = expf(sc[s * BB + b] - m);
            sd[s * BB + b] = e;
            ss += e;
        }
        float inv = 1.f / ss;
        for (int s = 0; s <= t; s++) {
            float dv = sd[s * BB + b] * inv;
            sd[s * BB + b] = dv;
            if (blockIdx.x == 0) dist[s * BB + b] = dv;
        }
    }
    __syncthreads();
    int gi = blockIdx.x * 256 + tid;
    int b = gi & 31;
    float acc = 0.f;
    for (int s = 0; s <= t; s++)
        acc = fmaf(sd[s * BB + b], hbuf[(size_t)s * HB + gi], acc);
    sum[gi] = acc;
}

// ---------------- comb = sum of 4 partials ----------------
__global__ void k_fincomb(const float* __restrict__ cp, float* __restrict__ comb)
{
    int i = blockIdx.x * 256 + threadIdx.x;
    comb[i] = cp[i] + cp[HB + i] + cp[2 * HB + i] + cp[3 * HB + i];
}

// ---------------- reduce: S per batch, derive ce/f/cw ----------------
__global__ void k_reduce2(const float* __restrict__ red, const float* __restrict__ pexp,
                          float* __restrict__ ce, float* __restrict__ f,
                          float* __restrict__ cw)
{
    int b = threadIdx.x;
    float S = 0.f;
    for (int i = 0; i < 500; i++) S += red[i * BB + b];
    float inv = 1.f / S;
    float c = pexp[3 * BB + b] * inv;
    ce[b] = c * 1e-7f;
    f[b]  = (1.f - c) * inv;
    cw[b] = c;
}

// ---------------- out (log only) + fused copy fixup ----------------
__global__ void __launch_bounds__(256) k_out(const float* __restrict__ pexp,
        const float* __restrict__ ce, const float* __restrict__ f,
        const float* __restrict__ cw, const int* __restrict__ toks,
        const float* __restrict__ dist, float* __restrict__ out, int t)
{
    __shared__ float tile[128 * 33];
    int v0 = blockIdx.x * 128;                 // 250 blocks
    int lane = threadIdx.x & 31, w = threadIdx.x >> 5;
    float ceL = ce[lane], fL = f[lane];
#pragma unroll
    for (int k = 0; k < 16; k++) {
        int vr = (k << 3) + w;
        tile[vr * 33 + lane] = logf(ceL + fL * pexp[(size_t)(v0 + vr) * BB + lane]);
    }
    __syncthreads();
    int bo = threadIdx.x >> 3, q = threadIdx.x & 7;
    float* op = out + (size_t)(t * BB + bo) * VV + v0;
#pragma unroll
    for (int i = 0; i < 4; i++) {
        int vb = (q + (i << 3)) << 2;
        *(float4*)(op + vb) = make_float4(tile[vb * 33 + bo],
                                          tile[(vb + 1) * 33 + bo],
                                          tile[(vb + 2) * 33 + bo],
                                          tile[(vb + 3) * 33 + bo]);
    }
    __syncthreads();
    // copy-scatter fixup for tokens in this block's v-range
    float cwL = cw[lane];
    for (int s = w; s <= t; s += 8) {
        int v = toks[s * BB + lane];
        if (v >= v0 && v < v0 + 128) {
            bool first = true;
            for (int sp = 0; sp < s; sp++)
                if (toks[sp * BB + lane] == v) { first = false; break; }
            if (first) {
                float S = 0.f;
                for (int sp = s; sp <= t; sp++)
                    if (toks[sp * BB + lane] == v) S += dist[sp * BB + lane];
                out[(size_t)(t * BB + lane) * VV + v] =
                    logf(ceL + cwL * S + fL * pexp[(size_t)v * BB + lane]);
            }
        }
    }
}

// ---------------- host ----------------
extern "C" void kernel_launch(void* const* d_in, const int* in_sizes, int n_in,
                              void* d_out, int out_size)
{
    const int*   toks = (const int*)d_in[0];
    const float* h0   = (const float*)d_in[1];
    const float* c0   = (const float*)d_in[2];
    const float* E    = (const float*)d_in[3];
    const float* Wih0 = (const float*)d_in[4];
    const float* Whh0 = (const float*)d_in[5];
    const float* bih0 = (const float*)d_in[6];
    const float* bhh0 = (const float*)d_in[7];
    const float* Wih1 = (const float*)d_in[8];
    const float* Whh1 = (const float*)d_in[9];
    const float* bih1 = (const float*)d_in[10];
    const float* bhh1 = (const float*)d_in[11];
    const float* Wk   = (const float*)d_in[12];
    const float* bk   = (const float*)d_in[13];
    const float* Wc   = (const float*)d_in[14];
    const float* bc   = (const float*)d_in[15];
    const float* Wp   = (const float*)d_in[16];
    const float* bp   = (const float*)d_in[17];
    float* out = (float*)d_out;

    float *emb, *comb, *h0p, *h1i, *c0p, *c1p, *g, *kp, *cp, *hbuf, *keys;
    float *sc, *dist, *sumv, *pexp, *red, *ce, *f, *cw;
    cudaGetSymbolAddress((void**)&emb,  d_emb);
    cudaGetSymbolAddress((void**)&comb, d_comb);
    cudaGetSymbolAddress((void**)&h0p,  d_h0p);
    cudaGetSymbolAddress((void**)&h1i,  d_h1i);
    cudaGetSymbolAddress((void**)&c0p,  d_c0p);
    cudaGetSymbolAddress((void**)&c1p,  d_c1p);
    cudaGetSymbolAddress((void**)&g,    d_g);
    cudaGetSymbolAddress((void**)&kp,   d_kp);
    cudaGetSymbolAddress((void**)&cp,   d_cp);
    cudaGetSymbolAddress((void**)&hbuf, d_hbuf);
    cudaGetSymbolAddress((void**)&keys, d_keys);
    cudaGetSymbolAddress((void**)&sc,   d_sc);
    cudaGetSymbolAddress((void**)&dist, d_dist);
    cudaGetSymbolAddress((void**)&sumv, d_sumv);
    cudaGetSymbolAddress((void**)&pexp, d_pexp);
    cudaGetSymbolAddress((void**)&red,  d_red);
    cudaGetSymbolAddress((void**)&ce,   d_ce);
    cudaGetSymbolAddress((void**)&f,    d_f);
    cudaGetSymbolAddress((void**)&cw,   d_cw);

    static cudaStream_t sA = nullptr;
    static cudaEvent_t evC[2], evD[2], evJ;
    if (!sA) {
        cudaStreamCreateWithFlags(&sA, cudaStreamNonBlocking);
        for (int i = 0; i < 2; i++) {
            cudaEventCreateWithFlags(&evC[i], cudaEventDisableTiming);
            cudaEventCreateWithFlags(&evD[i], cudaEventDisableTiming);
        }
        cudaEventCreateWithFlags(&evJ, cudaEventDisableTiming);
    }

    const long long GP = (long long)G4 * BB;

    k_embed_all<<<(TS * EMBD * BB) / 256, 256>>>(E, toks, emb);
    k_init<<<HB / 256, 256>>>(h0, c0, h0p, h1i, c0p, c1p, comb);

    for (int t = 0; t < TS; t++) {
        float* htop = hbuf + (size_t)t * HB;
        const float* h1prev  = t ? hbuf + (size_t)(t - 1) * HB : h1i;
        const float* emb_t   = emb + (size_t)t * EMBD * BB;
        const float* combPrev = comb + (size_t)((t + 1) & 1) * HB;
        float*       combCur  = comb + (size_t)(t & 1) * HB;
        float*       distCur  = dist + (size_t)(t & 1) * TS * BB;

        // protect comb/dist ping-pong buffers from the side chain 2 steps back
        if (t >= 2) cudaStreamWaitEvent(0, evD[t & 1], 0);

        // ---- recurrence critical chain (stream 0) ----
        k_gemm<32><<<dim3(G4 / 32, 4), 256>>>(
            Wih0, emb_t, 1536, 16,
            Wih0 + 512, combPrev, 1536, 32,
            Whh0, h0p, 1024, 32,
            20, bih0, bhh0, g, GP);
        k_gates<<<HB / 256, 256>>>(g, c0p, h0p);

        k_gemm<32><<<dim3(G4 / 32, 4), 256>>>(
            Wih1, h0p, 1024, 32,
            Whh1, h1prev, 1024, 32,
            nullptr, nullptr, 0, 0,
            16, bih1, bhh1, g, GP);
        k_gates<<<HB / 256, 256>>>(g, c1p, htop);

        k_gemm<32><<<dim3(HH / 32, 4), 256>>>(
            Wk, htop, 1024, 32,
            nullptr, nullptr, 0, 0,
            nullptr, nullptr, 0, 0,
            8, bk, nullptr, kp, (long long)HB);
        k_scores<<<t + 1, 256>>>(keys, kp, htop, toks, sc, t);
        k_summary<<<HB / 256, 256>>>(sc, hbuf, t, distCur, sumv);

        k_gemm<32><<<dim3(HH / 32, 4), 256>>>(
            Wc, htop, 2048, 32,
            Wc + 1024, sumv, 2048, 32,
            nullptr, nullptr, 0, 0,
            16, bc, nullptr, cp, (long long)HB);
        k_fincomb<<<HB / 256, 256>>>(cp, combCur);
        cudaEventRecord(evC[t & 1], 0);

        // ---- side chain: logits / softmax / out / fixup (stream A) ----
        cudaStreamWaitEvent(sA, evC[t & 1], 0);
        k_logits<<<VV / 64, 256, 0, sA>>>(Wp, combCur, bp, pexp, red);
        k_reduce2<<<1, 32, 0, sA>>>(red, pexp, ce, f, cw);
        k_out<<<VV / 128, 256, 0, sA>>>(pexp, ce, f, cw, toks, distCur, out, t);
        cudaEventRecord(evD[t & 1], sA);
    }

    // join side chain back into the captured origin stream
    cudaStreamWaitEvent(0, evD[(TS - 1) & 1], 0);
    cudaStreamWaitEvent(0, evD[TS & 1], 0);
}

// round 8
// speedup vs baseline: 1.8159x; 1.1878x over previous
#include <cuda_runtime.h>
#include <math.h>

#define TS   64
#define BB   32
#define VV   32000
#define HH   1024
#define EMBD 512
#define G4   4096
#define HB   32768          // HH*BB

typedef unsigned long long ull;

// ---------------- device scratch ----------------
__device__ float d_emb[(size_t)TS * EMBD * BB];   // [t][k][b]
__device__ float d_comb[2 * HB];                  // ping-pong by t&1
__device__ float d_h0p[HB];
__device__ float d_h1i[HB];
__device__ float d_c0p[HB], d_c1p[HB];
__device__ float d_g[4 * (size_t)G4 * BB];        // 4 partial planes
__device__ float d_kp[4 * (size_t)HB];
__device__ float d_cp[4 * (size_t)HB];
__device__ float d_hbuf[(size_t)TS * HB];
__device__ float d_keys[(size_t)TS * HB];
__device__ float d_sc[TS * BB];
__device__ float d_dist[2 * TS * BB];
__device__ float d_sumv[HB];
__device__ float d_pexp[(size_t)VV * BB];
__device__ float d_red[500 * BB];
__device__ float d_ce[BB], d_f[BB], d_cw[BB];

// transposed weights [k][j]
__device__ float dT_ih0[1536 * G4];
__device__ float dT_hh0[HH * G4];
__device__ float dT_ih1[HH * G4];
__device__ float dT_hh1[HH * G4];
__device__ float dT_k[HH * HH];
__device__ float dT_c[2048 * HH];
__device__ float dT_p[(size_t)HH * VV];

__device__ __forceinline__ float sigm(float x) { return 1.f / (1.f + expf(-x)); }

__device__ __forceinline__ void ffma2(ull& d, ull a, ull x) {
    asm("fma.rn.f32x2 %0, %1, %2, %0;" : "+l"(d) : "l"(a), "l"(x));
}
__device__ __forceinline__ ull pack2(float x) {
    ull r; unsigned int xi = __float_as_uint(x);
    asm("mov.b64 %0, {%1, %1};" : "=l"(r) : "r"(xi));
    return r;
}
__device__ __forceinline__ void unpack2(ull v, float& lo, float& hi) {
    unsigned int a, b;
    asm("mov.b64 {%0, %1}, %2;" : "=r"(a), "=r"(b) : "l"(v));
    lo = __uint_as_float(a); hi = __uint_as_float(b);
}
__device__ __forceinline__ void cpa16(unsigned int s, const void* g) {
    asm volatile("cp.async.cg.shared.global [%0], [%1], 16;" :: "r"(s), "l"(g));
}
#define CP_COMMIT() asm volatile("cp.async.commit_group;")
#define CP_WAIT2()  asm volatile("cp.async.wait_group 2;")
#define CP_WAIT0()  asm volatile("cp.async.wait_group 0;")

// ---------------- transpose-all kernel ----------------
struct TransTab { const float* s[7]; float* d[7]; int J[7]; int K[7]; };

__global__ void __launch_bounds__(256) k_trans(TransTab tt)
{
    __shared__ float sm[32][33];
    int id = blockIdx.x;
    int m = 0;
    int jt, kt;
    for (;;) {
        jt = tt.J[m] >> 5; kt = tt.K[m] >> 5;
        int n = jt * kt;
        if (id < n) break;
        id -= n; m++;
    }
    const float* src = tt.s[m];
    float* dst = tt.d[m];
    int J = tt.J[m], K = tt.K[m];
    int kT = id / jt, jT = id - kT * jt;
    int j0 = jT << 5, k0 = kT << 5;
    int r = threadIdx.x >> 3, c4 = (threadIdx.x & 7) << 2;
    float4 v = *(const float4*)(src + (size_t)(j0 + r) * K + k0 + c4);
    sm[r][c4 + 0] = v.x; sm[r][c4 + 1] = v.y;
    sm[r][c4 + 2] = v.z; sm[r][c4 + 3] = v.w;
    __syncthreads();
    // write dst[k0+kk][j0+j4..]
    int kk = r, j4 = c4;
    *(float4*)(dst + (size_t)(k0 + kk) * J + j0 + j4) =
        make_float4(sm[j4][kk], sm[j4 + 1][kk], sm[j4 + 2][kk], sm[j4 + 3][kk]);
}

// ---------------- GEMM: A transposed [k][j], cp.async 4-stage pipeline -------
// out[y][j][b] over k-tiles [y*tps, ...). 256 threads, JT rows/block.
template<int JT>
__global__ void __launch_bounds__(256) k_gemm(
    const float* __restrict__ A0, const float* __restrict__ X0, int ldj0, int t0,
    const float* __restrict__ A1, const float* __restrict__ X1, int ldj1, int t1,
    const float* __restrict__ A2, const float* __restrict__ X2, int ldj2, int t2,
    int tps, const float* __restrict__ bias1, const float* __restrict__ bias2,
    float* __restrict__ out, long long outPlane)
{
    constexpr int R   = JT / 8;
    constexpr int PR  = R / 2;
    constexpr int ASZ = 32 * JT;
    constexpr int XSZ = 32 * 32;

    __shared__ __align__(16) float As[4][ASZ];
    __shared__ __align__(16) float Xs[4][XSZ];

    const int tid = threadIdx.x;
    const int b   = tid & 31, rg = tid >> 5;
    const int j0  = blockIdx.x * JT;
    const int total = t0 + t1 + t2;
    const int g0 = blockIdx.y * tps;
    const int g1 = min(total, g0 + tps);

    unsigned int sA = (unsigned int)__cvta_generic_to_shared(As);
    unsigned int sX = (unsigned int)__cvta_generic_to_shared(Xs);

    auto issue = [&](int g, int st) {
        const float* A; const float* X; int ldj, lk;
        if (g < t0)           { A = A0; X = X0; ldj = ldj0; lk = g; }
        else if (g < t0 + t1) { A = A1; X = X1; ldj = ldj1; lk = g - t0; }
        else                  { A = A2; X = X2; ldj = ldj2; lk = g - t0 - t1; }
        const int k0 = lk << 5;
#pragma unroll
        for (int i = 0; i < JT / 32; i++) {
            int c = tid + 256 * i;
            int kk = c / (JT / 4), jq = (c % (JT / 4)) << 2;
            cpa16(sA + (st * ASZ + kk * JT + jq) * 4,
                  A + (size_t)(k0 + kk) * ldj + j0 + jq);
        }
        {
            int kk = tid >> 3, bq = (tid & 7) << 2;
            cpa16(sX + (st * XSZ + kk * 32 + bq) * 4,
                  X + (size_t)(k0 + kk) * BB + bq);
        }
    };

    ull acc[PR];
#pragma unroll
    for (int p = 0; p < PR; p++) acc[p] = 0ull;

    const int nReal = g1 - g0;
    for (int i = 0; i < 3; i++) {
        if (i < nReal) issue(g0 + i, i);
        CP_COMMIT();
    }
    for (int g = g0; g < g1; g++) {
        const int st = (g - g0) & 3;
        CP_WAIT2();
        __syncthreads();
        if (g + 3 < g1) issue(g + 3, (g - g0 + 3) & 3);
        CP_COMMIT();
        const float* A_ = As[st];
        const float* X_ = Xs[st];
#pragma unroll
        for (int kk = 0; kk < 32; kk++) {
            ull xp = pack2(X_[kk * 32 + b]);
            const float* ab = A_ + kk * JT + rg * R;
#pragma unroll
            for (int q = 0; q < PR / 2; q++) {
                ulonglong2 u = *(const ulonglong2*)(ab + (q << 2));
                ffma2(acc[2 * q],     u.x, xp);
                ffma2(acc[2 * q + 1], u.y, xp);
            }
        }
    }
    CP_WAIT0();

    float* outp = out + blockIdx.y * outPlane;
#pragma unroll
    for (int p = 0; p < PR; p++) {
        float lo, hi;
        unpack2(acc[p], lo, hi);
        const int j = j0 + rg * R + 2 * p;
        if (blockIdx.y == 0) {
            if (bias1) { lo += bias1[j]; hi += bias1[j + 1]; }
            if (bias2) { lo += bias2[j]; hi += bias2[j + 1]; }
        }
        outp[(size_t)j * BB + b]       = lo;
        outp[(size_t)(j + 1) * BB + b] = hi;
    }
}

// ---------------- logits: JT=64 pipelined GEMM + exp epilogue + block sum ----
__global__ void __launch_bounds__(256) k_logits(
    const float* __restrict__ AT, const float* __restrict__ comb,
    const float* __restrict__ bp, float* __restrict__ pexp, float* __restrict__ red)
{
    constexpr int JT = 64, ASZ = 32 * 64, XSZ = 32 * 32;
    __shared__ __align__(16) float As[4][ASZ];
    __shared__ __align__(16) float Xs[4][XSZ];
    __shared__ float sr[8][33];

    const int tid = threadIdx.x;
    const int b   = tid & 31, rg = tid >> 5;
    const int j0  = blockIdx.x * JT;
    unsigned int sA = (unsigned int)__cvta_generic_to_shared(As);
    unsigned int sX = (unsigned int)__cvta_generic_to_shared(Xs);

    auto issue = [&](int g, int st) {
        const int k0 = g << 5;
#pragma unroll
        for (int i = 0; i < 2; i++) {
            int c = tid + 256 * i;
            int kk = c >> 4, jq = (c & 15) << 2;
            cpa16(sA + (st * ASZ + kk * JT + jq) * 4,
                  AT + (size_t)(k0 + kk) * VV + j0 + jq);
        }
        {
            int kk = tid >> 3, bq = (tid & 7) << 2;
            cpa16(sX + (st * XSZ + kk * 32 + bq) * 4,
                  comb + (size_t)(k0 + kk) * BB + bq);
        }
    };

    ull acc4[4] = {0ull, 0ull, 0ull, 0ull};
    for (int i = 0; i < 3; i++) { issue(i, i); CP_COMMIT(); }
    for (int g = 0; g < 32; g++) {
        const int st = g & 3;
        CP_WAIT2();
        __syncthreads();
        if (g + 3 < 32) issue(g + 3, (g + 3) & 3);
        CP_COMMIT();
        const float* A_ = As[st];
        const float* X_ = Xs[st];
#pragma unroll
        for (int kk = 0; kk < 32; kk++) {
            ull xp = pack2(X_[kk * 32 + b]);
            const float* ab = A_ + kk * JT + rg * 8;
            ulonglong2 u0 = *(const ulonglong2*)(ab);
            ulonglong2 u1 = *(const ulonglong2*)(ab + 4);
            ffma2(acc4[0], u0.x, xp);
            ffma2(acc4[1], u0.y, xp);
            ffma2(acc4[2], u1.x, xp);
            ffma2(acc4[3], u1.y, xp);
        }
    }
    CP_WAIT0();

    float psum = 0.f;
#pragma unroll
    for (int p = 0; p < 4; p++) {
        float lo, hi; unpack2(acc4[p], lo, hi);
        int j = j0 + rg * 8 + 2 * p;
        float e0 = expf(lo + bp[j]);
        float e1 = expf(hi + bp[j + 1]);
        pexp[(size_t)j * BB + b]       = e0;
        pexp[(size_t)(j + 1) * BB + b] = e1;
        psum += e0 + e1;
    }
    sr[rg][b] = psum;
    __syncthreads();
    if (tid < 32) {
        float v = 0.f;
#pragma unroll
        for (int r = 0; r < 8; r++) v += sr[r][tid];
        red[blockIdx.x * BB + tid] = v;
    }
}

// ---------------- embed all timesteps once ----------------
__global__ void k_embed_all(const float* __restrict__ E, const int* __restrict__ toks,
                            float* __restrict__ emb)
{
    int i = blockIdx.x * 256 + threadIdx.x;
    int b = i & 31, k = (i >> 5) & (EMBD - 1), t = i >> 14;
    emb[i] = E[(size_t)toks[t * BB + b] * EMBD + k];
}

// ---------------- init ----------------
__global__ void k_init(const float* __restrict__ h0, const float* __restrict__ c0,
                       float* h0p, float* h1i, float* c0p, float* c1p, float* comb)
{
    int i = blockIdx.x * 256 + threadIdx.x;
    int h = i >> 5, b = i & 31;
    h0p[i]  = h0[(size_t)b * HH + h];
    h1i[i]  = h0[(size_t)(BB + b) * HH + h];
    c0p[i]  = c0[(size_t)b * HH + h];
    c1p[i]  = c0[(size_t)(BB + b) * HH + h];
    comb[i] = 0.f;
    comb[HB + i] = 0.f;
}

// ---------------- LSTM gates ----------------
__global__ void k_gates(const float* __restrict__ gp, float* __restrict__ c,
                        float* __restrict__ hout)
{
    int i = blockIdx.x * 256 + threadIdx.x;
    float g[4];
#pragma unroll
    for (int m = 0; m < 4; m++) {
        size_t o = (size_t)m * HB + i;
        g[m] = gp[o] + gp[(size_t)G4 * BB + o] + gp[2 * (size_t)G4 * BB + o]
             + gp[3 * (size_t)G4 * BB + o];
    }
    float c2 = sigm(g[1]) * c[i] + sigm(g[0]) * tanhf(g[2]);
    c[i] = c2;
    hout[i] = sigm(g[3]) * tanhf(c2);
}

// ---------------- scores (+ finalize keys[t]) ----------------
__global__ void __launch_bounds__(256) k_scores(float* __restrict__ keys,
        const float* __restrict__ kp, const float* __restrict__ htop,
        const int* __restrict__ toks, float* __restrict__ sc, int t)
{
    int s = blockIdx.x;
    int lane = threadIdx.x & 31, w = threadIdx.x >> 5;
    float acc = 0.f;
    if (s == t) {
        float* kf = keys + (size_t)t * HB;
        for (int h = w; h < HH; h += 8) {
            int i = h * BB + lane;
            float v = kp[i] + kp[HB + i] + kp[2 * HB + i] + kp[3 * HB + i];
            kf[i] = v;
            acc = fmaf(v, htop[i], acc);
        }
    } else {
        const float* ks = keys + (size_t)s * HB;
        for (int h = w; h < HH; h += 8)
            acc = fmaf(ks[h * BB + lane], htop[h * BB + lane], acc);
    }
    __shared__ float red[8][BB];
    red[w][lane] = acc;
    __syncthreads();
    if (w == 0) {
        float v = acc;
#pragma unroll
        for (int r = 1; r < 8; r++) v += red[r][lane];
        if (toks[s * BB + lane] == 0) v -= 99999.f;
        sc[s * BB + lane] = v;
    }
}

// ---------------- summary (softmax once in smem) ----------------
__global__ void k_summary(const float* __restrict__ sc, const float* __restrict__ hbuf,
                          int t, float* __restrict__ dist, float* __restrict__ sum)
{
    __shared__ float sd[TS * BB];
    int tid = threadIdx.x;
    if (tid < 32) {
        int b = tid;
        float m = -1e30f;
        for (int s = 0; s <= t; s++) m = fmaxf(m, sc[s * BB + b]);
        float ss = 0.f;
        for (int s = 0; s <= t; s++) {
            float e = expf(sc[s * BB + b] - m);
            sd[s * BB + b] = e;
            ss += e;
        }
        float inv = 1.f / ss;
        for (int s = 0; s <= t; s++) {
            float dv = sd[s * BB + b] * inv;
            sd[s * BB + b] = dv;
            if (blockIdx.x == 0) dist[s * BB + b] = dv;
        }
    }
    __syncthreads();
    int gi = blockIdx.x * 256 + tid;
    int b = gi & 31;
    float acc = 0.f;
    for (int s = 0; s <= t; s++)
        acc = fmaf(sd[s * BB + b], hbuf[(size_t)s * HB + gi], acc);
    sum[gi] = acc;
}

// ---------------- comb finalize ----------------
__global__ void k_fincomb(const float* __restrict__ cp, float* __restrict__ comb)
{
    int i = blockIdx.x * 256 + threadIdx.x;
    comb[i] = cp[i] + cp[HB + i] + cp[2 * HB + i] + cp[3 * HB + i];
}

// ---------------- softmax scalars ----------------
__global__ void k_reduce2(const float* __restrict__ red, const float* __restrict__ pexp,
                          float* __restrict__ ce, float* __restrict__ f,
                          float* __restrict__ cw)
{
    int b = threadIdx.x;
    float S = 0.f;
    for (int i = 0; i < 500; i++) S += red[i * BB + b];
    float inv = 1.f / S;
    float c = pexp[3 * BB + b] * inv;
    ce[b] = c * 1e-7f;
    f[b]  = (1.f - c) * inv;
    cw[b] = c;
}

// ---------------- out + fused fixup ----------------
__global__ void __launch_bounds__(256) k_out(const float* __restrict__ pexp,
        const float* __restrict__ ce, const float* __restrict__ f,
        const float* __restrict__ cw, const int* __restrict__ toks,
        const float* __restrict__ dist, float* __restrict__ out, int t)
{
    __shared__ float tile[128 * 33];
    int v0 = blockIdx.x * 128;
    int lane = threadIdx.x & 31, w = threadIdx.x >> 5;
    float ceL = ce[lane], fL = f[lane];
#pragma unroll
    for (int k = 0; k < 16; k++) {
        int vr = (k << 3) + w;
        tile[vr * 33 + lane] = logf(ceL + fL * pexp[(size_t)(v0 + vr) * BB + lane]);
    }
    __syncthreads();
    int bo = threadIdx.x >> 3, q = threadIdx.x & 7;
    float* op = out + (size_t)(t * BB + bo) * VV + v0;
#pragma unroll
    for (int i = 0; i < 4; i++) {
        int vb = (q + (i << 3)) << 2;
        *(float4*)(op + vb) = make_float4(tile[vb * 33 + bo],
                                          tile[(vb + 1) * 33 + bo],
                                          tile[(vb + 2) * 33 + bo],
                                          tile[(vb + 3) * 33 + bo]);
    }
    __syncthreads();
    float cwL = cw[lane];
    for (int s = w; s <= t; s += 8) {
        int v = toks[s * BB + lane];
        if (v >= v0 && v < v0 + 128) {
            bool first = true;
            for (int sp = 0; sp < s; sp++)
                if (toks[sp * BB + lane] == v) { first = false; break; }
            if (first) {
                float S = 0.f;
                for (int sp = s; sp <= t; sp++)
                    if (toks[sp * BB + lane] == v) S += dist[sp * BB + lane];
                out[(size_t)(t * BB + lane) * VV + v] =
                    logf(ceL + cwL * S + fL * pexp[(size_t)v * BB + lane]);
            }
        }
    }
}

// ---------------- host ----------------
extern "C" void kernel_launch(void* const* d_in, const int* in_sizes, int n_in,
                              void* d_out, int out_size)
{
    const int*   toks = (const int*)d_in[0];
    const float* h0   = (const float*)d_in[1];
    const float* c0   = (const float*)d_in[2];
    const float* E    = (const float*)d_in[3];
    const float* Wih0 = (const float*)d_in[4];
    const float* Whh0 = (const float*)d_in[5];
    const float* bih0 = (const float*)d_in[6];
    const float* bhh0 = (const float*)d_in[7];
    const float* Wih1 = (const float*)d_in[8];
    const float* Whh1 = (const float*)d_in[9];
    const float* bih1 = (const float*)d_in[10];
    const float* bhh1 = (const float*)d_in[11];
    const float* Wk   = (const float*)d_in[12];
    const float* bk   = (const float*)d_in[13];
    const float* Wc   = (const float*)d_in[14];
    const float* bc   = (const float*)d_in[15];
    const float* Wp   = (const float*)d_in[16];
    const float* bp   = (const float*)d_in[17];
    float* out = (float*)d_out;

    float *emb, *comb, *h0p, *h1i, *c0p, *c1p, *g, *kp, *cp, *hbuf, *keys;
    float *sc, *dist, *sumv, *pexp, *red, *ce, *f, *cw;
    float *Tih0, *Thh0, *Tih1, *Thh1, *Tk, *Tc, *Tp;
    cudaGetSymbolAddress((void**)&emb,  d_emb);
    cudaGetSymbolAddress((void**)&comb, d_comb);
    cudaGetSymbolAddress((void**)&h0p,  d_h0p);
    cudaGetSymbolAddress((void**)&h1i,  d_h1i);
    cudaGetSymbolAddress((void**)&c0p,  d_c0p);
    cudaGetSymbolAddress((void**)&c1p,  d_c1p);
    cudaGetSymbolAddress((void**)&g,    d_g);
    cudaGetSymbolAddress((void**)&kp,   d_kp);
    cudaGetSymbolAddress((void**)&cp,   d_cp);
    cudaGetSymbolAddress((void**)&hbuf, d_hbuf);
    cudaGetSymbolAddress((void**)&keys, d_keys);
    cudaGetSymbolAddress((void**)&sc,   d_sc);
    cudaGetSymbolAddress((void**)&dist, d_dist);
    cudaGetSymbolAddress((void**)&sumv, d_sumv);
    cudaGetSymbolAddress((void**)&pexp, d_pexp);
    cudaGetSymbolAddress((void**)&red,  d_red);
    cudaGetSymbolAddress((void**)&ce,   d_ce);
    cudaGetSymbolAddress((void**)&f,    d_f);
    cudaGetSymbolAddress((void**)&cw,   d_cw);
    cudaGetSymbolAddress((void**)&Tih0, dT_ih0);
    cudaGetSymbolAddress((void**)&Thh0, dT_hh0);
    cudaGetSymbolAddress((void**)&Tih1, dT_ih1);
    cudaGetSymbolAddress((void**)&Thh1, dT_hh1);
    cudaGetSymbolAddress((void**)&Tk,   dT_k);
    cudaGetSymbolAddress((void**)&Tc,   dT_c);
    cudaGetSymbolAddress((void**)&Tp,   dT_p);

    static cudaStream_t sA = nullptr;
    static cudaEvent_t evC[2], evD[2];
    if (!sA) {
        cudaStreamCreateWithFlags(&sA, cudaStreamNonBlocking);
        for (int i = 0; i < 2; i++) {
            cudaEventCreateWithFlags(&evC[i], cudaEventDisableTiming);
            cudaEventCreateWithFlags(&evD[i], cudaEventDisableTiming);
        }
    }

    const long long GP = (long long)G4 * BB;

    k_embed_all<<<(TS * EMBD * BB) / 256, 256>>>(E, toks, emb);
    k_init<<<HB / 256, 256>>>(h0, c0, h0p, h1i, c0p, c1p, comb);

    TransTab tt;
    tt.s[0] = Wih0; tt.d[0] = Tih0; tt.J[0] = G4; tt.K[0] = 1536;
    tt.s[1] = Whh0; tt.d[1] = Thh0; tt.J[1] = G4; tt.K[1] = HH;
    tt.s[2] = Wih1; tt.d[2] = Tih1; tt.J[2] = G4; tt.K[2] = HH;
    tt.s[3] = Whh1; tt.d[3] = Thh1; tt.J[3] = G4; tt.K[3] = HH;
    tt.s[4] = Wk;   tt.d[4] = Tk;   tt.J[4] = HH; tt.K[4] = HH;
    tt.s[5] = Wc;   tt.d[5] = Tc;   tt.J[5] = HH; tt.K[5] = 2048;
    tt.s[6] = Wp;   tt.d[6] = Tp;   tt.J[6] = VV; tt.K[6] = HH;
    int ntiles = 0;
    for (int m = 0; m < 7; m++) ntiles += (tt.J[m] >> 5) * (tt.K[m] >> 5);
    k_trans<<<ntiles, 256>>>(tt);

    for (int t = 0; t < TS; t++) {
        float* htop = hbuf + (size_t)t * HB;
        const float* h1prev   = t ? hbuf + (size_t)(t - 1) * HB : h1i;
        const float* emb_t    = emb + (size_t)t * EMBD * BB;
        const float* combPrev = comb + (size_t)((t + 1) & 1) * HB;
        float*       combCur  = comb + (size_t)(t & 1) * HB;
        float*       distCur  = dist + (size_t)(t & 1) * TS * BB;

        if (t >= 2) cudaStreamWaitEvent(0, evD[t & 1], 0);

        // LSTM0: 80 tiles (emb 16 | comb 32 | h0 32), 4 splits x 20
        k_gemm<32><<<dim3(G4 / 32, 4), 256>>>(
            Tih0, emb_t, G4, 16,
            Tih0 + (size_t)512 * G4, combPrev, G4, 32,
            Thh0, h0p, G4, 32,
            20, bih0, bhh0, g, GP);
        k_gates<<<HB / 256, 256>>>(g, c0p, h0p);

        // LSTM1: 64 tiles, 4 splits x 16
        k_gemm<32><<<dim3(G4 / 32, 4), 256>>>(
            Tih1, h0p, G4, 32,
            Thh1, h1prev, G4, 32,
            nullptr, nullptr, 0, 0,
            16, bih1, bhh1, g, GP);
        k_gates<<<HB / 256, 256>>>(g, c1p, htop);

        // keys[t]: 32 tiles, 4 splits x 8
        k_gemm<32><<<dim3(HH / 32, 4), 256>>>(
            Tk, htop, HH, 32,
            nullptr, nullptr, 0, 0,
            nullptr, nullptr, 0, 0,
            8, bk, nullptr, kp, (long long)HB);
        k_scores<<<t + 1, 256>>>(keys, kp, htop, toks, sc, t);
        k_summary<<<HB / 256, 256>>>(sc, hbuf, t, distCur, sumv);

        // comb: 64 tiles (htop 32 | sumv 32), 4 splits x 16
        k_gemm<32><<<dim3(HH / 32, 4), 256>>>(
            Tc, htop, HH, 32,
            Tc + (size_t)1024 * HH, sumv, HH, 32,
            nullptr, nullptr, 0, 0,
            16, bc, nullptr, cp, (long long)HB);
        k_fincomb<<<HB / 256, 256>>>(cp, combCur);
        cudaEventRecord(evC[t & 1], 0);

        // side chain (stream A)
        cudaStreamWaitEvent(sA, evC[t & 1], 0);
        k_logits<<<VV / 64, 256, 0, sA>>>(Tp, combCur, bp, pexp, red);
        k_reduce2<<<1, 32, 0, sA>>>(red, pexp, ce, f, cw);
        k_out<<<VV / 128, 256, 0, sA>>>(pexp, ce, f, cw, toks, distCur, out, t);
        cudaEventRecord(evD[t & 1], sA);
    }

    cudaStreamWaitEvent(0, evD[(TS - 1) & 1], 0);
    cudaStreamWaitEvent(0, evD[TS & 1], 0);
}